// round 4
// baseline (speedup 1.0000x reference)
#include <cuda_runtime.h>
#include <math.h>

// Problem constants
constexpr int B  = 4;
constexpr int L  = 2048;
constexpr int D  = 1024;
constexpr int H  = 16;
constexpr int HD = 64;
constexpr int BH = B * H;          // 64
constexpr long OUT_ELEMS  = (long)B * L * D;        // 8,388,608
constexpr long ATTN_ELEMS = (long)B * H * L * L;    // 268,435,456

// Scratch (device globals: allocation-free per harness rules)
__device__ __align__(16) float g_q [B * H * L * HD];   // [B,H,L,HD]
__device__ __align__(16) float g_k [B * H * L * HD];
__device__ __align__(16) float g_v [B * H * L * HD];
__device__ __align__(16) float g_oh[(long)B * L * D];  // [B,L,H*HD] = [B*L, D]

// ---------------------------------------------------------------------------
// Generic NT GEMM: C[M,N] = alpha * A[M,K] * B[N,K]^T (+ bias[N])
// BM=BN=128, BK=8, 256 threads, 8x8 per thread.
// out_mode 0: C[bz*strideC + r*N + c]
// out_mode 1: head-split store: (i -> b,l ; j -> h,hd) -> C[((b*H+h)*L+l)*HD+hd]
// ---------------------------------------------------------------------------
__global__ void __launch_bounds__(256)
gemm_nt_kernel(const float* __restrict__ A, const float* __restrict__ Bm,
               const float* __restrict__ bias, float* __restrict__ C,
               int M, int N, int K, float alpha,
               long strideA, long strideB, long strideC, int out_mode)
{
    constexpr int BM = 128, BN = 128, BK = 8;
    __shared__ float As[BK][BM];
    __shared__ float Bs[BK][BN];

    const int bz = blockIdx.z;
    A  += (long)bz * strideA;
    Bm += (long)bz * strideB;

    const int tid = threadIdx.x;
    const int tx  = tid % 16;   // N direction
    const int ty  = tid / 16;   // M direction
    const int row0 = blockIdx.y * BM;
    const int col0 = blockIdx.x * BN;

    // load mapping: 128 rows x 8 k per tile; each thread one float4 along K
    const int lr = tid >> 1;            // 0..127
    const int lc = (tid & 1) * 4;       // 0 or 4

    float acc[8][8];
    #pragma unroll
    for (int i = 0; i < 8; i++)
        #pragma unroll
        for (int j = 0; j < 8; j++) acc[i][j] = 0.f;

    for (int k0 = 0; k0 < K; k0 += BK) {
        const float4 a4 = *reinterpret_cast<const float4*>(&A [(long)(row0 + lr) * K + k0 + lc]);
        const float4 b4 = *reinterpret_cast<const float4*>(&Bm[(long)(col0 + lr) * K + k0 + lc]);
        As[lc + 0][lr] = a4.x; As[lc + 1][lr] = a4.y; As[lc + 2][lr] = a4.z; As[lc + 3][lr] = a4.w;
        Bs[lc + 0][lr] = b4.x; Bs[lc + 1][lr] = b4.y; Bs[lc + 2][lr] = b4.z; Bs[lc + 3][lr] = b4.w;
        __syncthreads();

        #pragma unroll
        for (int kk = 0; kk < BK; kk++) {
            float ra[8], rb[8];
            #pragma unroll
            for (int i = 0; i < 8; i++) ra[i] = As[kk][ty * 8 + i];
            #pragma unroll
            for (int j = 0; j < 8; j++) rb[j] = Bs[kk][tx * 8 + j];
            #pragma unroll
            for (int i = 0; i < 8; i++)
                #pragma unroll
                for (int j = 0; j < 8; j++)
                    acc[i][j] = fmaf(ra[i], rb[j], acc[i][j]);
        }
        __syncthreads();
    }

    #pragma unroll
    for (int i = 0; i < 8; i++) {
        const int r = row0 + ty * 8 + i;
        #pragma unroll
        for (int j = 0; j < 8; j++) {
            const int c = col0 + tx * 8 + j;
            float val = acc[i][j] * alpha;
            if (bias) val += bias[c];
            if (out_mode == 0) {
                C[(long)bz * strideC + (long)r * N + c] = val;
            } else {
                // r = b*L + l ; c = h*HD + hd
                const int b  = r >> 11;        // / L
                const int l  = r & (L - 1);
                const int h  = c >> 6;         // / HD
                const int hd = c & (HD - 1);
                C[(((long)(b * H + h)) * L + l) * HD + hd] = val;
            }
        }
    }
}

// ---------------------------------------------------------------------------
// In-place row softmax: grid.x = B*H*L rows, 256 threads, row length L=2048
// ---------------------------------------------------------------------------
__global__ void __launch_bounds__(256)
softmax_kernel(float* __restrict__ attn)
{
    const long row = blockIdx.x;
    float* p = attn + row * (long)L;
    const int tid = threadIdx.x;

    float v[8];
    float m = -INFINITY;
    #pragma unroll
    for (int i = 0; i < 8; i++) {
        v[i] = p[tid + i * 256];
        m = fmaxf(m, v[i]);
    }

    __shared__ float red[256];
    red[tid] = m;
    __syncthreads();
    #pragma unroll
    for (int s = 128; s > 0; s >>= 1) {
        if (tid < s) red[tid] = fmaxf(red[tid], red[tid + s]);
        __syncthreads();
    }
    m = red[0];
    __syncthreads();

    float sum = 0.f;
    #pragma unroll
    for (int i = 0; i < 8; i++) {
        v[i] = expf(v[i] - m);
        sum += v[i];
    }
    red[tid] = sum;
    __syncthreads();
    #pragma unroll
    for (int s = 128; s > 0; s >>= 1) {
        if (tid < s) red[tid] += red[tid + s];
        __syncthreads();
    }
    const float inv = 1.f / red[0];

    #pragma unroll
    for (int i = 0; i < 8; i++)
        p[tid + i * 256] = v[i] * inv;
}

// ---------------------------------------------------------------------------
// PV: per (b,h): OH = P[L,L] @ V[L,HD]   (NN gemm)
// BM=128, BN=64, BK=16, 256 threads, 8x4 per thread. Output layout [B,L,H,HD].
// ---------------------------------------------------------------------------
__global__ void __launch_bounds__(256)
pv_kernel(const float* __restrict__ Pfull, const float* __restrict__ Vfull,
          float* __restrict__ OH)
{
    constexpr int BM = 128, BK = 16;
    const int bh = blockIdx.z;
    const int b  = bh / H;
    const int h  = bh % H;
    const float* P = Pfull + (long)bh * L * L;
    const float* V = Vfull + (long)bh * L * HD;

    __shared__ float Ps[BK][BM];
    __shared__ float Vs[BK][HD];

    const int tid = threadIdx.x;
    const int tx  = tid % 16;   // N direction (4 cols each)
    const int ty  = tid / 16;   // M direction (8 rows each)
    const int row0 = blockIdx.y * BM;

    // P load: 128x16 floats -> 8 per thread (two float4 along k)
    const int plr = tid >> 1;            // 0..127
    const int plc = (tid & 1) * 8;       // 0 or 8
    // V load: 16x64 floats -> one float4 per thread
    const int vr = tid / 16;             // 0..15
    const int vc = (tid % 16) * 4;       // 0..60

    float acc[8][4];
    #pragma unroll
    for (int i = 0; i < 8; i++)
        #pragma unroll
        for (int j = 0; j < 4; j++) acc[i][j] = 0.f;

    for (int k0 = 0; k0 < L; k0 += BK) {
        const float4 p0 = *reinterpret_cast<const float4*>(&P[(long)(row0 + plr) * L + k0 + plc]);
        const float4 p1 = *reinterpret_cast<const float4*>(&P[(long)(row0 + plr) * L + k0 + plc + 4]);
        Ps[plc + 0][plr] = p0.x; Ps[plc + 1][plr] = p0.y;
        Ps[plc + 2][plr] = p0.z; Ps[plc + 3][plr] = p0.w;
        Ps[plc + 4][plr] = p1.x; Ps[plc + 5][plr] = p1.y;
        Ps[plc + 6][plr] = p1.z; Ps[plc + 7][plr] = p1.w;
        *reinterpret_cast<float4*>(&Vs[vr][vc]) =
            *reinterpret_cast<const float4*>(&V[(long)(k0 + vr) * HD + vc]);
        __syncthreads();

        #pragma unroll
        for (int kk = 0; kk < BK; kk++) {
            float ra[8], rb[4];
            #pragma unroll
            for (int i = 0; i < 8; i++) ra[i] = Ps[kk][ty * 8 + i];
            #pragma unroll
            for (int j = 0; j < 4; j++) rb[j] = Vs[kk][tx * 4 + j];
            #pragma unroll
            for (int i = 0; i < 8; i++)
                #pragma unroll
                for (int j = 0; j < 4; j++)
                    acc[i][j] = fmaf(ra[i], rb[j], acc[i][j]);
        }
        __syncthreads();
    }

    #pragma unroll
    for (int i = 0; i < 8; i++) {
        const int l = row0 + ty * 8 + i;
        #pragma unroll
        for (int j = 0; j < 4; j++) {
            const int hd = tx * 4 + j;
            OH[((long)(b * L + l)) * D + h * HD + hd] = acc[i][j];
        }
    }
}

// ---------------------------------------------------------------------------
// Launch
// ---------------------------------------------------------------------------
extern "C" void kernel_launch(void* const* d_in, const int* in_sizes, int n_in,
                              void* d_out, int out_size)
{
    (void)in_sizes; (void)n_in; (void)out_size;
    const float* query = (const float*)d_in[0];
    const float* key   = (const float*)d_in[1];
    const float* value = (const float*)d_in[2];
    const float* Wq    = (const float*)d_in[3];
    const float* Wk    = (const float*)d_in[4];
    const float* Wv    = (const float*)d_in[5];
    const float* Wo    = (const float*)d_in[6];
    const float* bo    = (const float*)d_in[7];

    float* out  = (float*)d_out;
    float* attn = out + OUT_ELEMS;

    float *q_ptr, *k_ptr, *v_ptr, *oh_ptr;
    cudaGetSymbolAddress((void**)&q_ptr,  g_q);
    cudaGetSymbolAddress((void**)&k_ptr,  g_k);
    cudaGetSymbolAddress((void**)&v_ptr,  g_v);
    cudaGetSymbolAddress((void**)&oh_ptr, g_oh);

    const int M = B * L;  // 8192

    // 1) Projections: X @ W^T, head-split output
    {
        dim3 grid(D / 128, M / 128, 1);
        gemm_nt_kernel<<<grid, 256>>>(query, Wq, nullptr, q_ptr, M, D, D, 1.f, 0, 0, 0, 1);
        gemm_nt_kernel<<<grid, 256>>>(key,   Wk, nullptr, k_ptr, M, D, D, 1.f, 0, 0, 0, 1);
        gemm_nt_kernel<<<grid, 256>>>(value, Wv, nullptr, v_ptr, M, D, D, 1.f, 0, 0, 0, 1);
    }

    // 2) Logits = scale * Q K^T per (b,h) -> attention buffer (pre-softmax)
    {
        dim3 grid(L / 128, L / 128, BH);
        gemm_nt_kernel<<<grid, 256>>>(q_ptr, k_ptr, nullptr, attn,
                                      L, L, HD, 0.125f,
                                      (long)L * HD, (long)L * HD, (long)L * L, 0);
    }

    // 3) Row softmax in place
    softmax_kernel<<<(unsigned)((long)B * H * L), 256>>>(attn);

    // 4) OH = P @ V -> [B*L, D]
    {
        dim3 grid(1, L / 128, BH);
        pv_kernel<<<grid, 256>>>(attn, v_ptr, oh_ptr);
    }

    // 5) out = OH @ Wo^T + bo
    {
        dim3 grid(D / 128, M / 128, 1);
        gemm_nt_kernel<<<grid, 256>>>(oh_ptr, Wo, bo, out, M, D, D, 1.f, 0, 0, 0, 0);
    }
}

// round 5
// speedup vs baseline: 1.0005x; 1.0005x over previous
#include <cuda_runtime.h>
#include <math.h>

// Problem constants
constexpr int B  = 4;
constexpr int L  = 2048;
constexpr int D  = 1024;
constexpr int H  = 16;
constexpr int HD = 64;
constexpr int BH = B * H;          // 64
constexpr long OUT_ELEMS  = (long)B * L * D;        // 8,388,608
constexpr long ATTN_ELEMS = (long)B * H * L * L;    // 268,435,456

// Scratch (device globals: allocation-free per harness rules)
__device__ __align__(16) float g_q [B * H * L * HD];   // [B,H,L,HD]
__device__ __align__(16) float g_k [B * H * L * HD];
__device__ __align__(16) float g_v [B * H * L * HD];
__device__ __align__(16) float g_oh[(long)B * L * D];  // [B,L,H*HD] = [B*L, D]

// ---------------------------------------------------------------------------
// Generic NT GEMM: C[M,N] = alpha * A[M,K] * B[N,K]^T (+ bias[N])
// BM=BN=128, BK=8, 256 threads, 8x8 per thread.
// out_mode 0: C[bz*strideC + r*N + c]
// out_mode 1: head-split store: (i -> b,l ; j -> h,hd) -> C[((b*H+h)*L+l)*HD+hd]
// ---------------------------------------------------------------------------
__global__ void __launch_bounds__(256)
gemm_nt_kernel(const float* __restrict__ A, const float* __restrict__ Bm,
               const float* __restrict__ bias, float* __restrict__ C,
               int M, int N, int K, float alpha,
               long strideA, long strideB, long strideC, int out_mode)
{
    constexpr int BM = 128, BN = 128, BK = 8;
    __shared__ float As[BK][BM];
    __shared__ float Bs[BK][BN];

    const int bz = blockIdx.z;
    A  += (long)bz * strideA;
    Bm += (long)bz * strideB;

    const int tid = threadIdx.x;
    const int tx  = tid % 16;   // N direction
    const int ty  = tid / 16;   // M direction
    const int row0 = blockIdx.y * BM;
    const int col0 = blockIdx.x * BN;

    // load mapping: 128 rows x 8 k per tile; each thread one float4 along K
    const int lr = tid >> 1;            // 0..127
    const int lc = (tid & 1) * 4;       // 0 or 4

    float acc[8][8];
    #pragma unroll
    for (int i = 0; i < 8; i++)
        #pragma unroll
        for (int j = 0; j < 8; j++) acc[i][j] = 0.f;

    for (int k0 = 0; k0 < K; k0 += BK) {
        const float4 a4 = *reinterpret_cast<const float4*>(&A [(long)(row0 + lr) * K + k0 + lc]);
        const float4 b4 = *reinterpret_cast<const float4*>(&Bm[(long)(col0 + lr) * K + k0 + lc]);
        As[lc + 0][lr] = a4.x; As[lc + 1][lr] = a4.y; As[lc + 2][lr] = a4.z; As[lc + 3][lr] = a4.w;
        Bs[lc + 0][lr] = b4.x; Bs[lc + 1][lr] = b4.y; Bs[lc + 2][lr] = b4.z; Bs[lc + 3][lr] = b4.w;
        __syncthreads();

        #pragma unroll
        for (int kk = 0; kk < BK; kk++) {
            float ra[8], rb[8];
            #pragma unroll
            for (int i = 0; i < 8; i++) ra[i] = As[kk][ty * 8 + i];
            #pragma unroll
            for (int j = 0; j < 8; j++) rb[j] = Bs[kk][tx * 8 + j];
            #pragma unroll
            for (int i = 0; i < 8; i++)
                #pragma unroll
                for (int j = 0; j < 8; j++)
                    acc[i][j] = fmaf(ra[i], rb[j], acc[i][j]);
        }
        __syncthreads();
    }

    #pragma unroll
    for (int i = 0; i < 8; i++) {
        const int r = row0 + ty * 8 + i;
        #pragma unroll
        for (int j = 0; j < 8; j++) {
            const int c = col0 + tx * 8 + j;
            float val = acc[i][j] * alpha;
            if (bias) val += bias[c];
            if (out_mode == 0) {
                C[(long)bz * strideC + (long)r * N + c] = val;
            } else {
                // r = b*L + l ; c = h*HD + hd
                const int b  = r >> 11;        // / L
                const int l  = r & (L - 1);
                const int h  = c >> 6;         // / HD
                const int hd = c & (HD - 1);
                C[(((long)(b * H + h)) * L + l) * HD + hd] = val;
            }
        }
    }
}

// ---------------------------------------------------------------------------
// In-place row softmax: grid.x = B*H*L rows, 256 threads, row length L=2048
// ---------------------------------------------------------------------------
__global__ void __launch_bounds__(256)
softmax_kernel(float* __restrict__ attn)
{
    const long row = blockIdx.x;
    float* p = attn + row * (long)L;
    const int tid = threadIdx.x;

    float v[8];
    float m = -INFINITY;
    #pragma unroll
    for (int i = 0; i < 8; i++) {
        v[i] = p[tid + i * 256];
        m = fmaxf(m, v[i]);
    }

    __shared__ float red[256];
    red[tid] = m;
    __syncthreads();
    #pragma unroll
    for (int s = 128; s > 0; s >>= 1) {
        if (tid < s) red[tid] = fmaxf(red[tid], red[tid + s]);
        __syncthreads();
    }
    m = red[0];
    __syncthreads();

    float sum = 0.f;
    #pragma unroll
    for (int i = 0; i < 8; i++) {
        v[i] = expf(v[i] - m);
        sum += v[i];
    }
    red[tid] = sum;
    __syncthreads();
    #pragma unroll
    for (int s = 128; s > 0; s >>= 1) {
        if (tid < s) red[tid] += red[tid + s];
        __syncthreads();
    }
    const float inv = 1.f / red[0];

    #pragma unroll
    for (int i = 0; i < 8; i++)
        p[tid + i * 256] = v[i] * inv;
}

// ---------------------------------------------------------------------------
// PV: per (b,h): OH = P[L,L] @ V[L,HD]   (NN gemm)
// BM=128, BN=64, BK=16, 256 threads, 8x4 per thread. Output layout [B,L,H,HD].
// ---------------------------------------------------------------------------
__global__ void __launch_bounds__(256)
pv_kernel(const float* __restrict__ Pfull, const float* __restrict__ Vfull,
          float* __restrict__ OH)
{
    constexpr int BM = 128, BK = 16;
    const int bh = blockIdx.z;
    const int b  = bh / H;
    const int h  = bh % H;
    const float* P = Pfull + (long)bh * L * L;
    const float* V = Vfull + (long)bh * L * HD;

    __shared__ float Ps[BK][BM];
    __shared__ float Vs[BK][HD];

    const int tid = threadIdx.x;
    const int tx  = tid % 16;   // N direction (4 cols each)
    const int ty  = tid / 16;   // M direction (8 rows each)
    const int row0 = blockIdx.y * BM;

    // P load: 128x16 floats -> 8 per thread (two float4 along k)
    const int plr = tid >> 1;            // 0..127
    const int plc = (tid & 1) * 8;       // 0 or 8
    // V load: 16x64 floats -> one float4 per thread
    const int vr = tid / 16;             // 0..15
    const int vc = (tid % 16) * 4;       // 0..60

    float acc[8][4];
    #pragma unroll
    for (int i = 0; i < 8; i++)
        #pragma unroll
        for (int j = 0; j < 4; j++) acc[i][j] = 0.f;

    for (int k0 = 0; k0 < L; k0 += BK) {
        const float4 p0 = *reinterpret_cast<const float4*>(&P[(long)(row0 + plr) * L + k0 + plc]);
        const float4 p1 = *reinterpret_cast<const float4*>(&P[(long)(row0 + plr) * L + k0 + plc + 4]);
        Ps[plc + 0][plr] = p0.x; Ps[plc + 1][plr] = p0.y;
        Ps[plc + 2][plr] = p0.z; Ps[plc + 3][plr] = p0.w;
        Ps[plc + 4][plr] = p1.x; Ps[plc + 5][plr] = p1.y;
        Ps[plc + 6][plr] = p1.z; Ps[plc + 7][plr] = p1.w;
        *reinterpret_cast<float4*>(&Vs[vr][vc]) =
            *reinterpret_cast<const float4*>(&V[(long)(k0 + vr) * HD + vc]);
        __syncthreads();

        #pragma unroll
        for (int kk = 0; kk < BK; kk++) {
            float ra[8], rb[4];
            #pragma unroll
            for (int i = 0; i < 8; i++) ra[i] = Ps[kk][ty * 8 + i];
            #pragma unroll
            for (int j = 0; j < 4; j++) rb[j] = Vs[kk][tx * 4 + j];
            #pragma unroll
            for (int i = 0; i < 8; i++)
                #pragma unroll
                for (int j = 0; j < 4; j++)
                    acc[i][j] = fmaf(ra[i], rb[j], acc[i][j]);
        }
        __syncthreads();
    }

    #pragma unroll
    for (int i = 0; i < 8; i++) {
        const int l = row0 + ty * 8 + i;
        #pragma unroll
        for (int j = 0; j < 4; j++) {
            const int hd = tx * 4 + j;
            OH[((long)(b * L + l)) * D + h * HD + hd] = acc[i][j];
        }
    }
}

// ---------------------------------------------------------------------------
// Launch
// ---------------------------------------------------------------------------
extern "C" void kernel_launch(void* const* d_in, const int* in_sizes, int n_in,
                              void* d_out, int out_size)
{
    (void)in_sizes; (void)n_in; (void)out_size;
    const float* query = (const float*)d_in[0];
    const float* key   = (const float*)d_in[1];
    const float* value = (const float*)d_in[2];
    const float* Wq    = (const float*)d_in[3];
    const float* Wk    = (const float*)d_in[4];
    const float* Wv    = (const float*)d_in[5];
    const float* Wo    = (const float*)d_in[6];
    const float* bo    = (const float*)d_in[7];

    float* out  = (float*)d_out;
    float* attn = out + OUT_ELEMS;

    float *q_ptr, *k_ptr, *v_ptr, *oh_ptr;
    cudaGetSymbolAddress((void**)&q_ptr,  g_q);
    cudaGetSymbolAddress((void**)&k_ptr,  g_k);
    cudaGetSymbolAddress((void**)&v_ptr,  g_v);
    cudaGetSymbolAddress((void**)&oh_ptr, g_oh);

    const int M = B * L;  // 8192

    // 1) Projections: X @ W^T, head-split output
    {
        dim3 grid(D / 128, M / 128, 1);
        gemm_nt_kernel<<<grid, 256>>>(query, Wq, nullptr, q_ptr, M, D, D, 1.f, 0, 0, 0, 1);
        gemm_nt_kernel<<<grid, 256>>>(key,   Wk, nullptr, k_ptr, M, D, D, 1.f, 0, 0, 0, 1);
        gemm_nt_kernel<<<grid, 256>>>(value, Wv, nullptr, v_ptr, M, D, D, 1.f, 0, 0, 0, 1);
    }

    // 2) Logits = scale * Q K^T per (b,h) -> attention buffer (pre-softmax)
    {
        dim3 grid(L / 128, L / 128, BH);
        gemm_nt_kernel<<<grid, 256>>>(q_ptr, k_ptr, nullptr, attn,
                                      L, L, HD, 0.125f,
                                      (long)L * HD, (long)L * HD, (long)L * L, 0);
    }

    // 3) Row softmax in place
    softmax_kernel<<<(unsigned)((long)B * H * L), 256>>>(attn);

    // 4) OH = P @ V -> [B*L, D]
    {
        dim3 grid(1, L / 128, BH);
        pv_kernel<<<grid, 256>>>(attn, v_ptr, oh_ptr);
    }

    // 5) out = OH @ Wo^T + bo
    {
        dim3 grid(D / 128, M / 128, 1);
        gemm_nt_kernel<<<grid, 256>>>(oh_ptr, Wo, bo, out, M, D, D, 1.f, 0, 0, 0, 0);
    }
}

// round 6
// speedup vs baseline: 1.0015x; 1.0010x over previous
#include <cuda_runtime.h>
#include <math.h>

// Problem constants
constexpr int B  = 4;
constexpr int L  = 2048;
constexpr int D  = 1024;
constexpr int H  = 16;
constexpr int HD = 64;
constexpr int BH = B * H;          // 64
constexpr long OUT_ELEMS  = (long)B * L * D;        // 8,388,608
constexpr long ATTN_ELEMS = (long)B * H * L * L;    // 268,435,456

// Scratch (device globals: allocation-free per harness rules)
__device__ __align__(16) float g_q [B * H * L * HD];   // [B,H,L,HD]
__device__ __align__(16) float g_k [B * H * L * HD];
__device__ __align__(16) float g_v [B * H * L * HD];
__device__ __align__(16) float g_oh[(long)B * L * D];  // [B,L,H*HD] = [B*L, D]

// ---------------------------------------------------------------------------
// Generic NT GEMM: C[M,N] = alpha * A[M,K] * B[N,K]^T (+ bias[N])
// BM=BN=128, BK=8, 256 threads, 8x8 per thread.
// out_mode 0: C[bz*strideC + r*N + c]
// out_mode 1: head-split store: (i -> b,l ; j -> h,hd) -> C[((b*H+h)*L+l)*HD+hd]
// ---------------------------------------------------------------------------
__global__ void __launch_bounds__(256)
gemm_nt_kernel(const float* __restrict__ A, const float* __restrict__ Bm,
               const float* __restrict__ bias, float* __restrict__ C,
               int M, int N, int K, float alpha,
               long strideA, long strideB, long strideC, int out_mode)
{
    constexpr int BM = 128, BN = 128, BK = 8;
    __shared__ float As[BK][BM];
    __shared__ float Bs[BK][BN];

    const int bz = blockIdx.z;
    A  += (long)bz * strideA;
    Bm += (long)bz * strideB;

    const int tid = threadIdx.x;
    const int tx  = tid % 16;   // N direction
    const int ty  = tid / 16;   // M direction
    const int row0 = blockIdx.y * BM;
    const int col0 = blockIdx.x * BN;

    // load mapping: 128 rows x 8 k per tile; each thread one float4 along K
    const int lr = tid >> 1;            // 0..127
    const int lc = (tid & 1) * 4;       // 0 or 4

    float acc[8][8];
    #pragma unroll
    for (int i = 0; i < 8; i++)
        #pragma unroll
        for (int j = 0; j < 8; j++) acc[i][j] = 0.f;

    for (int k0 = 0; k0 < K; k0 += BK) {
        const float4 a4 = *reinterpret_cast<const float4*>(&A [(long)(row0 + lr) * K + k0 + lc]);
        const float4 b4 = *reinterpret_cast<const float4*>(&Bm[(long)(col0 + lr) * K + k0 + lc]);
        As[lc + 0][lr] = a4.x; As[lc + 1][lr] = a4.y; As[lc + 2][lr] = a4.z; As[lc + 3][lr] = a4.w;
        Bs[lc + 0][lr] = b4.x; Bs[lc + 1][lr] = b4.y; Bs[lc + 2][lr] = b4.z; Bs[lc + 3][lr] = b4.w;
        __syncthreads();

        #pragma unroll
        for (int kk = 0; kk < BK; kk++) {
            float ra[8], rb[8];
            #pragma unroll
            for (int i = 0; i < 8; i++) ra[i] = As[kk][ty * 8 + i];
            #pragma unroll
            for (int j = 0; j < 8; j++) rb[j] = Bs[kk][tx * 8 + j];
            #pragma unroll
            for (int i = 0; i < 8; i++)
                #pragma unroll
                for (int j = 0; j < 8; j++)
                    acc[i][j] = fmaf(ra[i], rb[j], acc[i][j]);
        }
        __syncthreads();
    }

    #pragma unroll
    for (int i = 0; i < 8; i++) {
        const int r = row0 + ty * 8 + i;
        #pragma unroll
        for (int j = 0; j < 8; j++) {
            const int c = col0 + tx * 8 + j;
            float val = acc[i][j] * alpha;
            if (bias) val += bias[c];
            if (out_mode == 0) {
                C[(long)bz * strideC + (long)r * N + c] = val;
            } else {
                // r = b*L + l ; c = h*HD + hd
                const int b  = r >> 11;        // / L
                const int l  = r & (L - 1);
                const int h  = c >> 6;         // / HD
                const int hd = c & (HD - 1);
                C[(((long)(b * H + h)) * L + l) * HD + hd] = val;
            }
        }
    }
}

// ---------------------------------------------------------------------------
// In-place row softmax: grid.x = B*H*L rows, 256 threads, row length L=2048
// ---------------------------------------------------------------------------
__global__ void __launch_bounds__(256)
softmax_kernel(float* __restrict__ attn)
{
    const long row = blockIdx.x;
    float* p = attn + row * (long)L;
    const int tid = threadIdx.x;

    float v[8];
    float m = -INFINITY;
    #pragma unroll
    for (int i = 0; i < 8; i++) {
        v[i] = p[tid + i * 256];
        m = fmaxf(m, v[i]);
    }

    __shared__ float red[256];
    red[tid] = m;
    __syncthreads();
    #pragma unroll
    for (int s = 128; s > 0; s >>= 1) {
        if (tid < s) red[tid] = fmaxf(red[tid], red[tid + s]);
        __syncthreads();
    }
    m = red[0];
    __syncthreads();

    float sum = 0.f;
    #pragma unroll
    for (int i = 0; i < 8; i++) {
        v[i] = expf(v[i] - m);
        sum += v[i];
    }
    red[tid] = sum;
    __syncthreads();
    #pragma unroll
    for (int s = 128; s > 0; s >>= 1) {
        if (tid < s) red[tid] += red[tid + s];
        __syncthreads();
    }
    const float inv = 1.f / red[0];

    #pragma unroll
    for (int i = 0; i < 8; i++)
        p[tid + i * 256] = v[i] * inv;
}

// ---------------------------------------------------------------------------
// PV: per (b,h): OH = P[L,L] @ V[L,HD]   (NN gemm)
// BM=128, BN=64, BK=16, 256 threads, 8x4 per thread. Output layout [B,L,H,HD].
// ---------------------------------------------------------------------------
__global__ void __launch_bounds__(256)
pv_kernel(const float* __restrict__ Pfull, const float* __restrict__ Vfull,
          float* __restrict__ OH)
{
    constexpr int BM = 128, BK = 16;
    const int bh = blockIdx.z;
    const int b  = bh / H;
    const int h  = bh % H;
    const float* P = Pfull + (long)bh * L * L;
    const float* V = Vfull + (long)bh * L * HD;

    __shared__ float Ps[BK][BM];
    __shared__ float Vs[BK][HD];

    const int tid = threadIdx.x;
    const int tx  = tid % 16;   // N direction (4 cols each)
    const int ty  = tid / 16;   // M direction (8 rows each)
    const int row0 = blockIdx.y * BM;

    // P load: 128x16 floats -> 8 per thread (two float4 along k)
    const int plr = tid >> 1;            // 0..127
    const int plc = (tid & 1) * 8;       // 0 or 8
    // V load: 16x64 floats -> one float4 per thread
    const int vr = tid / 16;             // 0..15
    const int vc = (tid % 16) * 4;       // 0..60

    float acc[8][4];
    #pragma unroll
    for (int i = 0; i < 8; i++)
        #pragma unroll
        for (int j = 0; j < 4; j++) acc[i][j] = 0.f;

    for (int k0 = 0; k0 < L; k0 += BK) {
        const float4 p0 = *reinterpret_cast<const float4*>(&P[(long)(row0 + plr) * L + k0 + plc]);
        const float4 p1 = *reinterpret_cast<const float4*>(&P[(long)(row0 + plr) * L + k0 + plc + 4]);
        Ps[plc + 0][plr] = p0.x; Ps[plc + 1][plr] = p0.y;
        Ps[plc + 2][plr] = p0.z; Ps[plc + 3][plr] = p0.w;
        Ps[plc + 4][plr] = p1.x; Ps[plc + 5][plr] = p1.y;
        Ps[plc + 6][plr] = p1.z; Ps[plc + 7][plr] = p1.w;
        *reinterpret_cast<float4*>(&Vs[vr][vc]) =
            *reinterpret_cast<const float4*>(&V[(long)(k0 + vr) * HD + vc]);
        __syncthreads();

        #pragma unroll
        for (int kk = 0; kk < BK; kk++) {
            float ra[8], rb[4];
            #pragma unroll
            for (int i = 0; i < 8; i++) ra[i] = Ps[kk][ty * 8 + i];
            #pragma unroll
            for (int j = 0; j < 4; j++) rb[j] = Vs[kk][tx * 4 + j];
            #pragma unroll
            for (int i = 0; i < 8; i++)
                #pragma unroll
                for (int j = 0; j < 4; j++)
                    acc[i][j] = fmaf(ra[i], rb[j], acc[i][j]);
        }
        __syncthreads();
    }

    #pragma unroll
    for (int i = 0; i < 8; i++) {
        const int l = row0 + ty * 8 + i;
        #pragma unroll
        for (int j = 0; j < 4; j++) {
            const int hd = tx * 4 + j;
            OH[((long)(b * L + l)) * D + h * HD + hd] = acc[i][j];
        }
    }
}

// ---------------------------------------------------------------------------
// Launch
// ---------------------------------------------------------------------------
extern "C" void kernel_launch(void* const* d_in, const int* in_sizes, int n_in,
                              void* d_out, int out_size)
{
    (void)in_sizes; (void)n_in; (void)out_size;
    const float* query = (const float*)d_in[0];
    const float* key   = (const float*)d_in[1];
    const float* value = (const float*)d_in[2];
    const float* Wq    = (const float*)d_in[3];
    const float* Wk    = (const float*)d_in[4];
    const float* Wv    = (const float*)d_in[5];
    const float* Wo    = (const float*)d_in[6];
    const float* bo    = (const float*)d_in[7];

    float* out  = (float*)d_out;
    float* attn = out + OUT_ELEMS;

    float *q_ptr, *k_ptr, *v_ptr, *oh_ptr;
    cudaGetSymbolAddress((void**)&q_ptr,  g_q);
    cudaGetSymbolAddress((void**)&k_ptr,  g_k);
    cudaGetSymbolAddress((void**)&v_ptr,  g_v);
    cudaGetSymbolAddress((void**)&oh_ptr, g_oh);

    const int M = B * L;  // 8192

    // 1) Projections: X @ W^T, head-split output
    {
        dim3 grid(D / 128, M / 128, 1);
        gemm_nt_kernel<<<grid, 256>>>(query, Wq, nullptr, q_ptr, M, D, D, 1.f, 0, 0, 0, 1);
        gemm_nt_kernel<<<grid, 256>>>(key,   Wk, nullptr, k_ptr, M, D, D, 1.f, 0, 0, 0, 1);
        gemm_nt_kernel<<<grid, 256>>>(value, Wv, nullptr, v_ptr, M, D, D, 1.f, 0, 0, 0, 1);
    }

    // 2) Logits = scale * Q K^T per (b,h) -> attention buffer (pre-softmax)
    {
        dim3 grid(L / 128, L / 128, BH);
        gemm_nt_kernel<<<grid, 256>>>(q_ptr, k_ptr, nullptr, attn,
                                      L, L, HD, 0.125f,
                                      (long)L * HD, (long)L * HD, (long)L * L, 0);
    }

    // 3) Row softmax in place
    softmax_kernel<<<(unsigned)((long)B * H * L), 256>>>(attn);

    // 4) OH = P @ V -> [B*L, D]
    {
        dim3 grid(1, L / 128, BH);
        pv_kernel<<<grid, 256>>>(attn, v_ptr, oh_ptr);
    }

    // 5) out = OH @ Wo^T + bo
    {
        dim3 grid(D / 128, M / 128, 1);
        gemm_nt_kernel<<<grid, 256>>>(oh_ptr, Wo, bo, out, M, D, D, 1.f, 0, 0, 0, 0);
    }
}

// round 7
// speedup vs baseline: 1.0018x; 1.0003x over previous
#include <cuda_runtime.h>
#include <math.h>

// Problem constants
constexpr int B  = 4;
constexpr int L  = 2048;
constexpr int D  = 1024;
constexpr int H  = 16;
constexpr int HD = 64;
constexpr int BH = B * H;          // 64
constexpr long OUT_ELEMS  = (long)B * L * D;        // 8,388,608
constexpr long ATTN_ELEMS = (long)B * H * L * L;    // 268,435,456

// Scratch (device globals: allocation-free per harness rules)
__device__ __align__(16) float g_q [B * H * L * HD];   // [B,H,L,HD]
__device__ __align__(16) float g_k [B * H * L * HD];
__device__ __align__(16) float g_v [B * H * L * HD];
__device__ __align__(16) float g_oh[(long)B * L * D];  // [B,L,H*HD] = [B*L, D]

// ---------------------------------------------------------------------------
// Generic NT GEMM: C[M,N] = alpha * A[M,K] * B[N,K]^T (+ bias[N])
// BM=BN=128, BK=8, 256 threads, 8x8 per thread.
// out_mode 0: C[bz*strideC + r*N + c]
// out_mode 1: head-split store: (i -> b,l ; j -> h,hd) -> C[((b*H+h)*L+l)*HD+hd]
// ---------------------------------------------------------------------------
__global__ void __launch_bounds__(256)
gemm_nt_kernel(const float* __restrict__ A, const float* __restrict__ Bm,
               const float* __restrict__ bias, float* __restrict__ C,
               int M, int N, int K, float alpha,
               long strideA, long strideB, long strideC, int out_mode)
{
    constexpr int BM = 128, BN = 128, BK = 8;
    __shared__ float As[BK][BM];
    __shared__ float Bs[BK][BN];

    const int bz = blockIdx.z;
    A  += (long)bz * strideA;
    Bm += (long)bz * strideB;

    const int tid = threadIdx.x;
    const int tx  = tid % 16;   // N direction
    const int ty  = tid / 16;   // M direction
    const int row0 = blockIdx.y * BM;
    const int col0 = blockIdx.x * BN;

    // load mapping: 128 rows x 8 k per tile; each thread one float4 along K
    const int lr = tid >> 1;            // 0..127
    const int lc = (tid & 1) * 4;       // 0 or 4

    float acc[8][8];
    #pragma unroll
    for (int i = 0; i < 8; i++)
        #pragma unroll
        for (int j = 0; j < 8; j++) acc[i][j] = 0.f;

    for (int k0 = 0; k0 < K; k0 += BK) {
        const float4 a4 = *reinterpret_cast<const float4*>(&A [(long)(row0 + lr) * K + k0 + lc]);
        const float4 b4 = *reinterpret_cast<const float4*>(&Bm[(long)(col0 + lr) * K + k0 + lc]);
        As[lc + 0][lr] = a4.x; As[lc + 1][lr] = a4.y; As[lc + 2][lr] = a4.z; As[lc + 3][lr] = a4.w;
        Bs[lc + 0][lr] = b4.x; Bs[lc + 1][lr] = b4.y; Bs[lc + 2][lr] = b4.z; Bs[lc + 3][lr] = b4.w;
        __syncthreads();

        #pragma unroll
        for (int kk = 0; kk < BK; kk++) {
            float ra[8], rb[8];
            #pragma unroll
            for (int i = 0; i < 8; i++) ra[i] = As[kk][ty * 8 + i];
            #pragma unroll
            for (int j = 0; j < 8; j++) rb[j] = Bs[kk][tx * 8 + j];
            #pragma unroll
            for (int i = 0; i < 8; i++)
                #pragma unroll
                for (int j = 0; j < 8; j++)
                    acc[i][j] = fmaf(ra[i], rb[j], acc[i][j]);
        }
        __syncthreads();
    }

    #pragma unroll
    for (int i = 0; i < 8; i++) {
        const int r = row0 + ty * 8 + i;
        #pragma unroll
        for (int j = 0; j < 8; j++) {
            const int c = col0 + tx * 8 + j;
            float val = acc[i][j] * alpha;
            if (bias) val += bias[c];
            if (out_mode == 0) {
                C[(long)bz * strideC + (long)r * N + c] = val;
            } else {
                // r = b*L + l ; c = h*HD + hd
                const int b  = r >> 11;        // / L
                const int l  = r & (L - 1);
                const int h  = c >> 6;         // / HD
                const int hd = c & (HD - 1);
                C[(((long)(b * H + h)) * L + l) * HD + hd] = val;
            }
        }
    }
}

// ---------------------------------------------------------------------------
// In-place row softmax: grid.x = B*H*L rows, 256 threads, row length L=2048
// ---------------------------------------------------------------------------
__global__ void __launch_bounds__(256)
softmax_kernel(float* __restrict__ attn)
{
    const long row = blockIdx.x;
    float* p = attn + row * (long)L;
    const int tid = threadIdx.x;

    float v[8];
    float m = -INFINITY;
    #pragma unroll
    for (int i = 0; i < 8; i++) {
        v[i] = p[tid + i * 256];
        m = fmaxf(m, v[i]);
    }

    __shared__ float red[256];
    red[tid] = m;
    __syncthreads();
    #pragma unroll
    for (int s = 128; s > 0; s >>= 1) {
        if (tid < s) red[tid] = fmaxf(red[tid], red[tid + s]);
        __syncthreads();
    }
    m = red[0];
    __syncthreads();

    float sum = 0.f;
    #pragma unroll
    for (int i = 0; i < 8; i++) {
        v[i] = expf(v[i] - m);
        sum += v[i];
    }
    red[tid] = sum;
    __syncthreads();
    #pragma unroll
    for (int s = 128; s > 0; s >>= 1) {
        if (tid < s) red[tid] += red[tid + s];
        __syncthreads();
    }
    const float inv = 1.f / red[0];

    #pragma unroll
    for (int i = 0; i < 8; i++)
        p[tid + i * 256] = v[i] * inv;
}

// ---------------------------------------------------------------------------
// PV: per (b,h): OH = P[L,L] @ V[L,HD]   (NN gemm)
// BM=128, BN=64, BK=16, 256 threads, 8x4 per thread. Output layout [B,L,H,HD].
// ---------------------------------------------------------------------------
__global__ void __launch_bounds__(256)
pv_kernel(const float* __restrict__ Pfull, const float* __restrict__ Vfull,
          float* __restrict__ OH)
{
    constexpr int BM = 128, BK = 16;
    const int bh = blockIdx.z;
    const int b  = bh / H;
    const int h  = bh % H;
    const float* P = Pfull + (long)bh * L * L;
    const float* V = Vfull + (long)bh * L * HD;

    __shared__ float Ps[BK][BM];
    __shared__ float Vs[BK][HD];

    const int tid = threadIdx.x;
    const int tx  = tid % 16;   // N direction (4 cols each)
    const int ty  = tid / 16;   // M direction (8 rows each)
    const int row0 = blockIdx.y * BM;

    // P load: 128x16 floats -> 8 per thread (two float4 along k)
    const int plr = tid >> 1;            // 0..127
    const int plc = (tid & 1) * 8;       // 0 or 8
    // V load: 16x64 floats -> one float4 per thread
    const int vr = tid / 16;             // 0..15
    const int vc = (tid % 16) * 4;       // 0..60

    float acc[8][4];
    #pragma unroll
    for (int i = 0; i < 8; i++)
        #pragma unroll
        for (int j = 0; j < 4; j++) acc[i][j] = 0.f;

    for (int k0 = 0; k0 < L; k0 += BK) {
        const float4 p0 = *reinterpret_cast<const float4*>(&P[(long)(row0 + plr) * L + k0 + plc]);
        const float4 p1 = *reinterpret_cast<const float4*>(&P[(long)(row0 + plr) * L + k0 + plc + 4]);
        Ps[plc + 0][plr] = p0.x; Ps[plc + 1][plr] = p0.y;
        Ps[plc + 2][plr] = p0.z; Ps[plc + 3][plr] = p0.w;
        Ps[plc + 4][plr] = p1.x; Ps[plc + 5][plr] = p1.y;
        Ps[plc + 6][plr] = p1.z; Ps[plc + 7][plr] = p1.w;
        *reinterpret_cast<float4*>(&Vs[vr][vc]) =
            *reinterpret_cast<const float4*>(&V[(long)(k0 + vr) * HD + vc]);
        __syncthreads();

        #pragma unroll
        for (int kk = 0; kk < BK; kk++) {
            float ra[8], rb[4];
            #pragma unroll
            for (int i = 0; i < 8; i++) ra[i] = Ps[kk][ty * 8 + i];
            #pragma unroll
            for (int j = 0; j < 4; j++) rb[j] = Vs[kk][tx * 4 + j];
            #pragma unroll
            for (int i = 0; i < 8; i++)
                #pragma unroll
                for (int j = 0; j < 4; j++)
                    acc[i][j] = fmaf(ra[i], rb[j], acc[i][j]);
        }
        __syncthreads();
    }

    #pragma unroll
    for (int i = 0; i < 8; i++) {
        const int l = row0 + ty * 8 + i;
        #pragma unroll
        for (int j = 0; j < 4; j++) {
            const int hd = tx * 4 + j;
            OH[((long)(b * L + l)) * D + h * HD + hd] = acc[i][j];
        }
    }
}

// ---------------------------------------------------------------------------
// Launch
// ---------------------------------------------------------------------------
extern "C" void kernel_launch(void* const* d_in, const int* in_sizes, int n_in,
                              void* d_out, int out_size)
{
    (void)in_sizes; (void)n_in; (void)out_size;
    const float* query = (const float*)d_in[0];
    const float* key   = (const float*)d_in[1];
    const float* value = (const float*)d_in[2];
    const float* Wq    = (const float*)d_in[3];
    const float* Wk    = (const float*)d_in[4];
    const float* Wv    = (const float*)d_in[5];
    const float* Wo    = (const float*)d_in[6];
    const float* bo    = (const float*)d_in[7];

    float* out  = (float*)d_out;
    float* attn = out + OUT_ELEMS;

    float *q_ptr, *k_ptr, *v_ptr, *oh_ptr;
    cudaGetSymbolAddress((void**)&q_ptr,  g_q);
    cudaGetSymbolAddress((void**)&k_ptr,  g_k);
    cudaGetSymbolAddress((void**)&v_ptr,  g_v);
    cudaGetSymbolAddress((void**)&oh_ptr, g_oh);

    const int M = B * L;  // 8192

    // 1) Projections: X @ W^T, head-split output
    {
        dim3 grid(D / 128, M / 128, 1);
        gemm_nt_kernel<<<grid, 256>>>(query, Wq, nullptr, q_ptr, M, D, D, 1.f, 0, 0, 0, 1);
        gemm_nt_kernel<<<grid, 256>>>(key,   Wk, nullptr, k_ptr, M, D, D, 1.f, 0, 0, 0, 1);
        gemm_nt_kernel<<<grid, 256>>>(value, Wv, nullptr, v_ptr, M, D, D, 1.f, 0, 0, 0, 1);
    }

    // 2) Logits = scale * Q K^T per (b,h) -> attention buffer (pre-softmax)
    {
        dim3 grid(L / 128, L / 128, BH);
        gemm_nt_kernel<<<grid, 256>>>(q_ptr, k_ptr, nullptr, attn,
                                      L, L, HD, 0.125f,
                                      (long)L * HD, (long)L * HD, (long)L * L, 0);
    }

    // 3) Row softmax in place
    softmax_kernel<<<(unsigned)((long)B * H * L), 256>>>(attn);

    // 4) OH = P @ V -> [B*L, D]
    {
        dim3 grid(1, L / 128, BH);
        pv_kernel<<<grid, 256>>>(attn, v_ptr, oh_ptr);
    }

    // 5) out = OH @ Wo^T + bo
    {
        dim3 grid(D / 128, M / 128, 1);
        gemm_nt_kernel<<<grid, 256>>>(oh_ptr, Wo, bo, out, M, D, D, 1.f, 0, 0, 0, 0);
    }
}

// round 8
// speedup vs baseline: 1.0022x; 1.0005x over previous
#include <cuda_runtime.h>
#include <math.h>

// Problem constants
constexpr int B  = 4;
constexpr int L  = 2048;
constexpr int D  = 1024;
constexpr int H  = 16;
constexpr int HD = 64;
constexpr int BH = B * H;          // 64
constexpr long OUT_ELEMS  = (long)B * L * D;        // 8,388,608
constexpr long ATTN_ELEMS = (long)B * H * L * L;    // 268,435,456

// Scratch (device globals: allocation-free per harness rules)
__device__ __align__(16) float g_q [B * H * L * HD];   // [B,H,L,HD]
__device__ __align__(16) float g_k [B * H * L * HD];
__device__ __align__(16) float g_v [B * H * L * HD];
__device__ __align__(16) float g_oh[(long)B * L * D];  // [B,L,H*HD] = [B*L, D]

// ---------------------------------------------------------------------------
// Generic NT GEMM: C[M,N] = alpha * A[M,K] * B[N,K]^T (+ bias[N])
// BM=BN=128, BK=8, 256 threads, 8x8 per thread.
// out_mode 0: C[bz*strideC + r*N + c]
// out_mode 1: head-split store: (i -> b,l ; j -> h,hd) -> C[((b*H+h)*L+l)*HD+hd]
// ---------------------------------------------------------------------------
__global__ void __launch_bounds__(256)
gemm_nt_kernel(const float* __restrict__ A, const float* __restrict__ Bm,
               const float* __restrict__ bias, float* __restrict__ C,
               int M, int N, int K, float alpha,
               long strideA, long strideB, long strideC, int out_mode)
{
    constexpr int BM = 128, BN = 128, BK = 8;
    __shared__ float As[BK][BM];
    __shared__ float Bs[BK][BN];

    const int bz = blockIdx.z;
    A  += (long)bz * strideA;
    Bm += (long)bz * strideB;

    const int tid = threadIdx.x;
    const int tx  = tid % 16;   // N direction
    const int ty  = tid / 16;   // M direction
    const int row0 = blockIdx.y * BM;
    const int col0 = blockIdx.x * BN;

    // load mapping: 128 rows x 8 k per tile; each thread one float4 along K
    const int lr = tid >> 1;            // 0..127
    const int lc = (tid & 1) * 4;       // 0 or 4

    float acc[8][8];
    #pragma unroll
    for (int i = 0; i < 8; i++)
        #pragma unroll
        for (int j = 0; j < 8; j++) acc[i][j] = 0.f;

    for (int k0 = 0; k0 < K; k0 += BK) {
        const float4 a4 = *reinterpret_cast<const float4*>(&A [(long)(row0 + lr) * K + k0 + lc]);
        const float4 b4 = *reinterpret_cast<const float4*>(&Bm[(long)(col0 + lr) * K + k0 + lc]);
        As[lc + 0][lr] = a4.x; As[lc + 1][lr] = a4.y; As[lc + 2][lr] = a4.z; As[lc + 3][lr] = a4.w;
        Bs[lc + 0][lr] = b4.x; Bs[lc + 1][lr] = b4.y; Bs[lc + 2][lr] = b4.z; Bs[lc + 3][lr] = b4.w;
        __syncthreads();

        #pragma unroll
        for (int kk = 0; kk < BK; kk++) {
            float ra[8], rb[8];
            #pragma unroll
            for (int i = 0; i < 8; i++) ra[i] = As[kk][ty * 8 + i];
            #pragma unroll
            for (int j = 0; j < 8; j++) rb[j] = Bs[kk][tx * 8 + j];
            #pragma unroll
            for (int i = 0; i < 8; i++)
                #pragma unroll
                for (int j = 0; j < 8; j++)
                    acc[i][j] = fmaf(ra[i], rb[j], acc[i][j]);
        }
        __syncthreads();
    }

    #pragma unroll
    for (int i = 0; i < 8; i++) {
        const int r = row0 + ty * 8 + i;
        #pragma unroll
        for (int j = 0; j < 8; j++) {
            const int c = col0 + tx * 8 + j;
            float val = acc[i][j] * alpha;
            if (bias) val += bias[c];
            if (out_mode == 0) {
                C[(long)bz * strideC + (long)r * N + c] = val;
            } else {
                // r = b*L + l ; c = h*HD + hd
                const int b  = r >> 11;        // / L
                const int l  = r & (L - 1);
                const int h  = c >> 6;         // / HD
                const int hd = c & (HD - 1);
                C[(((long)(b * H + h)) * L + l) * HD + hd] = val;
            }
        }
    }
}

// ---------------------------------------------------------------------------
// In-place row softmax: grid.x = B*H*L rows, 256 threads, row length L=2048
// ---------------------------------------------------------------------------
__global__ void __launch_bounds__(256)
softmax_kernel(float* __restrict__ attn)
{
    const long row = blockIdx.x;
    float* p = attn + row * (long)L;
    const int tid = threadIdx.x;

    float v[8];
    float m = -INFINITY;
    #pragma unroll
    for (int i = 0; i < 8; i++) {
        v[i] = p[tid + i * 256];
        m = fmaxf(m, v[i]);
    }

    __shared__ float red[256];
    red[tid] = m;
    __syncthreads();
    #pragma unroll
    for (int s = 128; s > 0; s >>= 1) {
        if (tid < s) red[tid] = fmaxf(red[tid], red[tid + s]);
        __syncthreads();
    }
    m = red[0];
    __syncthreads();

    float sum = 0.f;
    #pragma unroll
    for (int i = 0; i < 8; i++) {
        v[i] = expf(v[i] - m);
        sum += v[i];
    }
    red[tid] = sum;
    __syncthreads();
    #pragma unroll
    for (int s = 128; s > 0; s >>= 1) {
        if (tid < s) red[tid] += red[tid + s];
        __syncthreads();
    }
    const float inv = 1.f / red[0];

    #pragma unroll
    for (int i = 0; i < 8; i++)
        p[tid + i * 256] = v[i] * inv;
}

// ---------------------------------------------------------------------------
// PV: per (b,h): OH = P[L,L] @ V[L,HD]   (NN gemm)
// BM=128, BN=64, BK=16, 256 threads, 8x4 per thread. Output layout [B,L,H,HD].
// ---------------------------------------------------------------------------
__global__ void __launch_bounds__(256)
pv_kernel(const float* __restrict__ Pfull, const float* __restrict__ Vfull,
          float* __restrict__ OH)
{
    constexpr int BM = 128, BK = 16;
    const int bh = blockIdx.z;
    const int b  = bh / H;
    const int h  = bh % H;
    const float* P = Pfull + (long)bh * L * L;
    const float* V = Vfull + (long)bh * L * HD;

    __shared__ float Ps[BK][BM];
    __shared__ float Vs[BK][HD];

    const int tid = threadIdx.x;
    const int tx  = tid % 16;   // N direction (4 cols each)
    const int ty  = tid / 16;   // M direction (8 rows each)
    const int row0 = blockIdx.y * BM;

    // P load: 128x16 floats -> 8 per thread (two float4 along k)
    const int plr = tid >> 1;            // 0..127
    const int plc = (tid & 1) * 8;       // 0 or 8
    // V load: 16x64 floats -> one float4 per thread
    const int vr = tid / 16;             // 0..15
    const int vc = (tid % 16) * 4;       // 0..60

    float acc[8][4];
    #pragma unroll
    for (int i = 0; i < 8; i++)
        #pragma unroll
        for (int j = 0; j < 4; j++) acc[i][j] = 0.f;

    for (int k0 = 0; k0 < L; k0 += BK) {
        const float4 p0 = *reinterpret_cast<const float4*>(&P[(long)(row0 + plr) * L + k0 + plc]);
        const float4 p1 = *reinterpret_cast<const float4*>(&P[(long)(row0 + plr) * L + k0 + plc + 4]);
        Ps[plc + 0][plr] = p0.x; Ps[plc + 1][plr] = p0.y;
        Ps[plc + 2][plr] = p0.z; Ps[plc + 3][plr] = p0.w;
        Ps[plc + 4][plr] = p1.x; Ps[plc + 5][plr] = p1.y;
        Ps[plc + 6][plr] = p1.z; Ps[plc + 7][plr] = p1.w;
        *reinterpret_cast<float4*>(&Vs[vr][vc]) =
            *reinterpret_cast<const float4*>(&V[(long)(k0 + vr) * HD + vc]);
        __syncthreads();

        #pragma unroll
        for (int kk = 0; kk < BK; kk++) {
            float ra[8], rb[4];
            #pragma unroll
            for (int i = 0; i < 8; i++) ra[i] = Ps[kk][ty * 8 + i];
            #pragma unroll
            for (int j = 0; j < 4; j++) rb[j] = Vs[kk][tx * 4 + j];
            #pragma unroll
            for (int i = 0; i < 8; i++)
                #pragma unroll
                for (int j = 0; j < 4; j++)
                    acc[i][j] = fmaf(ra[i], rb[j], acc[i][j]);
        }
        __syncthreads();
    }

    #pragma unroll
    for (int i = 0; i < 8; i++) {
        const int l = row0 + ty * 8 + i;
        #pragma unroll
        for (int j = 0; j < 4; j++) {
            const int hd = tx * 4 + j;
            OH[((long)(b * L + l)) * D + h * HD + hd] = acc[i][j];
        }
    }
}

// ---------------------------------------------------------------------------
// Launch
// ---------------------------------------------------------------------------
extern "C" void kernel_launch(void* const* d_in, const int* in_sizes, int n_in,
                              void* d_out, int out_size)
{
    (void)in_sizes; (void)n_in; (void)out_size;
    const float* query = (const float*)d_in[0];
    const float* key   = (const float*)d_in[1];
    const float* value = (const float*)d_in[2];
    const float* Wq    = (const float*)d_in[3];
    const float* Wk    = (const float*)d_in[4];
    const float* Wv    = (const float*)d_in[5];
    const float* Wo    = (const float*)d_in[6];
    const float* bo    = (const float*)d_in[7];

    float* out  = (float*)d_out;
    float* attn = out + OUT_ELEMS;

    float *q_ptr, *k_ptr, *v_ptr, *oh_ptr;
    cudaGetSymbolAddress((void**)&q_ptr,  g_q);
    cudaGetSymbolAddress((void**)&k_ptr,  g_k);
    cudaGetSymbolAddress((void**)&v_ptr,  g_v);
    cudaGetSymbolAddress((void**)&oh_ptr, g_oh);

    const int M = B * L;  // 8192

    // 1) Projections: X @ W^T, head-split output
    {
        dim3 grid(D / 128, M / 128, 1);
        gemm_nt_kernel<<<grid, 256>>>(query, Wq, nullptr, q_ptr, M, D, D, 1.f, 0, 0, 0, 1);
        gemm_nt_kernel<<<grid, 256>>>(key,   Wk, nullptr, k_ptr, M, D, D, 1.f, 0, 0, 0, 1);
        gemm_nt_kernel<<<grid, 256>>>(value, Wv, nullptr, v_ptr, M, D, D, 1.f, 0, 0, 0, 1);
    }

    // 2) Logits = scale * Q K^T per (b,h) -> attention buffer (pre-softmax)
    {
        dim3 grid(L / 128, L / 128, BH);
        gemm_nt_kernel<<<grid, 256>>>(q_ptr, k_ptr, nullptr, attn,
                                      L, L, HD, 0.125f,
                                      (long)L * HD, (long)L * HD, (long)L * L, 0);
    }

    // 3) Row softmax in place
    softmax_kernel<<<(unsigned)((long)B * H * L), 256>>>(attn);

    // 4) OH = P @ V -> [B*L, D]
    {
        dim3 grid(1, L / 128, BH);
        pv_kernel<<<grid, 256>>>(attn, v_ptr, oh_ptr);
    }

    // 5) out = OH @ Wo^T + bo
    {
        dim3 grid(D / 128, M / 128, 1);
        gemm_nt_kernel<<<grid, 256>>>(oh_ptr, Wo, bo, out, M, D, D, 1.f, 0, 0, 0, 0);
    }
}